// round 12
// baseline (speedup 1.0000x reference)
#include <cuda_runtime.h>
#include <cuda_fp16.h>
#include <cuda_bf16.h>

#define BATCH 256
#define NV 10475
#define NJ 55
#define PB 486            // pose basis = 54*9; 486 = 6*81
#define NC3 (NV*3)        // 31425
#define NC3P 31488        // padded cols
#define JOFF (BATCH*NC3)

// ---- scratch ----
__device__ float g_jreg[3465];              // (55,63): [vt|sh|ex]
__device__ unsigned g_pfh2[PB * 128];       // [k][bp]: half2(pf[2bp][k], pf[2bp+1][k])
__device__ float g_Arel[BATCH * NJ * 12];
__device__ float g_vpT[NC3P * BATCH];       // [col][b]

__constant__ int c_parents[NJ] = {
    -1, 0, 0, 0, 1, 2, 3, 4, 5, 6, 7, 8, 9, 9, 9, 12, 13, 14, 16, 17, 18, 19,
    15, 15, 15, 20, 25, 26, 20, 28, 29, 20, 31, 32, 20, 34, 35, 20, 37, 38,
    21, 40, 41, 21, 43, 44, 21, 46, 47, 21, 49, 50, 21, 52, 53};

__device__ __forceinline__ const float* joint_R(
    int j, int b, const float* wr, const float* bp, const float* jaw,
    const float* le, const float* re, const float* lh, const float* rh)
{
    if (j == 0)  return wr + b * 9;
    if (j <= 21) return bp + (b * 21 + (j - 1)) * 9;
    if (j == 22) return jaw + b * 9;
    if (j == 23) return le + b * 9;
    if (j == 24) return re + b * 9;
    if (j <= 39) return lh + (b * 15 + (j - 25)) * 9;
    return rh + (b * 15 + (j - 40)) * 9;
}

// ---- K1: fused JR @ [vt | shapedirs | expr_dirs] -> g_jreg (R3, verified) ----
__global__ __launch_bounds__(256) void jr_kernel(
    const float* __restrict__ JR, const float* __restrict__ vt,
    const float* __restrict__ sh, const float* __restrict__ ex)
{
    int j = blockIdx.x;
    int tid = threadIdx.x;
    __shared__ float jr_s[256];
    __shared__ float part[256];
    int c = tid % 63;
    int g = tid / 63;
    bool active = tid < 252;
    float acc = 0.f;

    for (int v0 = 0; v0 < NV; v0 += 256) {
        int vload = v0 + tid;
        jr_s[tid] = (vload < NV) ? JR[j * NV + vload] : 0.f;
        __syncthreads();
        if (active) {
            #pragma unroll 4
            for (int vv = g; vv < 256; vv += 4) {
                int gv = v0 + vv;
                if (gv < NV) {
                    float d;
                    if (c < 3)       d = vt[gv * 3 + c];
                    else if (c < 33) d = sh[gv * 30 + (c - 3)];
                    else             d = ex[gv * 30 + (c - 33)];
                    acc += jr_s[vv] * d;
                }
            }
        }
        __syncthreads();
    }
    part[tid] = active ? acc : 0.f;
    __syncthreads();
    if (tid < 63)
        g_jreg[j * 63 + tid] =
            part[tid] + part[63 + tid] + part[126 + tid] + part[189 + tid];
}

// ---- K2: chain + A_rel + joints out + pose-feature half write ----
__global__ __launch_bounds__(64) void chain_kernel(
    const float* __restrict__ wr, const float* __restrict__ bp,
    const float* __restrict__ jaw, const float* __restrict__ le,
    const float* __restrict__ re, const float* __restrict__ lh,
    const float* __restrict__ rh, const float* __restrict__ shape,
    const float* __restrict__ expr, const float* __restrict__ tsl,
    float* __restrict__ out)
{
    int b = blockIdx.x;
    int tid = threadIdx.x;
    __shared__ float R_s[NJ * 9];
    __shared__ float J_s[NJ * 3];
    __shared__ float rel_s[NJ * 3];
    __shared__ float A_s[NJ * 12];

    for (int idx = tid; idx < NJ * 9; idx += 64) {
        int j = idx / 9, e = idx % 9;
        R_s[idx] = joint_R(j, b, wr, bp, jaw, le, re, lh, rh)[e];
    }
    for (int idx = tid; idx < NJ * 3; idx += 64) {
        int j = idx / 3, c = idx % 3;
        const float* base = g_jreg + j * 63;
        float v = base[c];
        #pragma unroll
        for (int k = 0; k < 10; k++) v += base[3 + c * 10 + k] * shape[b * 10 + k];
        #pragma unroll
        for (int k = 0; k < 10; k++) v += base[33 + c * 10 + k] * expr[b * 10 + k];
        J_s[idx] = v;
    }
    __syncthreads();
    for (int idx = tid; idx < NJ * 3; idx += 64) {
        int j = idx / 3, c = idx % 3;
        rel_s[idx] = J_s[idx] - ((j > 0) ? J_s[c_parents[j] * 3 + c] : 0.f);
    }
    __syncthreads();

    if (tid < 12) {
        int r = tid / 4, c = tid % 4;
        A_s[r * 4 + c] = (c < 3) ? R_s[r * 3 + c] : rel_s[r];
        __syncwarp(0x0FFF);
        for (int i = 1; i < NJ; i++) {
            int p = c_parents[i];
            const float* Ap = A_s + p * 12;
            float v;
            if (c < 3)
                v = Ap[r * 4 + 0] * R_s[i * 9 + 0 + c] +
                    Ap[r * 4 + 1] * R_s[i * 9 + 3 + c] +
                    Ap[r * 4 + 2] * R_s[i * 9 + 6 + c];
            else
                v = Ap[r * 4 + 0] * rel_s[i * 3 + 0] +
                    Ap[r * 4 + 1] * rel_s[i * 3 + 1] +
                    Ap[r * 4 + 2] * rel_s[i * 3 + 2] + Ap[r * 4 + 3];
            A_s[i * 12 + r * 4 + c] = v;
            __syncwarp(0x0FFF);
        }
    }
    __syncthreads();

    // joints output
    for (int idx = tid; idx < NJ * 3; idx += 64) {
        int j = idx / 3, c = idx % 3;
        out[JOFF + b * (NJ * 3) + idx] = A_s[j * 12 + c * 4 + 3] + tsl[b * 3 + c];
    }
    // A_rel with corrected translation
    for (int idx = tid; idx < NJ * 12; idx += 64) {
        int j = idx / 12, e = idx % 12, r = e / 4, c = e % 4;
        float v;
        if (c < 3)
            v = A_s[j * 12 + r * 4 + c];
        else
            v = A_s[j * 12 + r * 4 + 3] -
                (A_s[j * 12 + r * 4 + 0] * J_s[j * 3 + 0] +
                 A_s[j * 12 + r * 4 + 1] * J_s[j * 3 + 1] +
                 A_s[j * 12 + r * 4 + 2] * J_s[j * 3 + 2]);
        g_Arel[b * (NJ * 12) + idx] = v;
    }
    // pose feature (R - I) as fp16 half, interleaved batch layout:
    // ((half*)g_pfh2)[k*256 + b]  == lane b of the k-th row
    {
        __half* pfh = (__half*)g_pfh2;
        for (int idx = tid; idx < PB; idx += 64) {
            int e = idx % 9;
            float v = R_s[9 + idx] - ((e == 0 || e == 4 || e == 8) ? 1.f : 0.f);
            pfh[idx * 256 + b] = __float2half_rn(v);
        }
    }
}

// ---- K3: HFMA2 GEMM g_vpT = pf @ posedirs (measured 171us, unchanged) ----
#define GC 24
#define GKC 81
#define GPROM 27

__global__ __launch_bounds__(256, 3) void gemmh_kernel(
    const float* __restrict__ posedirs)
{
    __shared__ __align__(16) unsigned pdh[GKC * GC];
    int tid = threadIdx.x;
    int w = tid >> 5, lane = tid & 31;
    int bpair = (w & 3) * 32 + lane;
    int cbase = (w >> 2) * 12;
    int col0 = blockIdx.x * GC;

    float2 accf[12];
    #pragma unroll
    for (int c = 0; c < 12; c++) accf[c] = make_float2(0.f, 0.f);

    for (int kc = 0; kc < 6; kc++) {
        int k0 = kc * GKC;
        for (int idx = tid; idx < GKC * GC; idx += 256) {
            int k = idx / GC, c = idx - k * GC;
            int gc = col0 + c;
            float v = (gc < NC3) ? posedirs[(k0 + k) * NC3 + gc] : 0.f;
            __half2 h = __half2half2(__float2half_rn(v));
            pdh[idx] = *(unsigned*)&h;
        }
        __syncthreads();

        const unsigned* pfb = g_pfh2 + k0 * 128 + bpair;
        for (int kp = 0; kp < GKC; kp += GPROM) {
            __half2 acch[12];
            #pragma unroll
            for (int c = 0; c < 12; c++) acch[c] = __half2half2(__ushort_as_half(0));
            #pragma unroll 9
            for (int k = 0; k < GPROM; k++) {
                int kk = kp + k;
                unsigned a2u = pfb[kk * 128];
                __half2 a2 = *(__half2*)&a2u;
                const uint4* prow = (const uint4*)(pdh + kk * GC + cbase);
                uint4 q0 = prow[0];
                uint4 q1 = prow[1];
                uint4 q2 = prow[2];
                unsigned pw[12] = {q0.x, q0.y, q0.z, q0.w,
                                   q1.x, q1.y, q1.z, q1.w,
                                   q2.x, q2.y, q2.z, q2.w};
                #pragma unroll
                for (int c = 0; c < 12; c++)
                    acch[c] = __hfma2(a2, *(__half2*)&pw[c], acch[c]);
            }
            #pragma unroll
            for (int c = 0; c < 12; c++) {
                float2 f = __half22float2(acch[c]);
                accf[c].x += f.x;
                accf[c].y += f.y;
            }
        }
        __syncthreads();
    }

    #pragma unroll
    for (int c = 0; c < 12; c++) {
        int gc = col0 + cbase + c;
        if (gc < NC3)
            *(float2*)(&g_vpT[gc * BATCH + 2 * bpair]) = accf[c];
    }
}

// ---- K4 (profiled slot): shape blend + skinning ----
#define BB 32
#define BV 64
#define JG 10
#define CS 193
#define SKIN_SMEM 10944

__global__ __launch_bounds__(256, 3) void skin_kernel(
    const float* __restrict__ v_template, const float* __restrict__ shapedirs,
    const float* __restrict__ expr_dirs, const float* __restrict__ lbsw,
    const float* __restrict__ body_shape, const float* __restrict__ expr_shape,
    const float* __restrict__ tsl, float* __restrict__ out_verts)
{
    int vt0 = blockIdx.x * BV;
    int b0 = blockIdx.y * BB;
    int tid = threadIdx.x;
    int vloc = tid & 31;
    int bg = tid >> 5;

    __shared__ __align__(16) float smem[SKIN_SMEM];
    float* c_s   = smem;
    float* sh_s  = smem + 6176;
    float* ex_s  = smem + 8096;
    float* vt_s  = smem + 10016;
    float* be_s  = smem + 10208;
    float* exb_s = smem + 10528;
    float* ts_s  = smem + 10848;

    int col0 = vt0 * 3;
    for (int idx = tid; idx < BB * 192; idx += 256) {
        int col = idx >> 5, bb = idx & 31;
        c_s[bb * CS + col] = g_vpT[(col0 + col) * BATCH + b0 + bb];
    }
    for (int idx = tid; idx < 1920; idx += 256) {
        int v = idx / 30, e = idx % 30;
        int gv = vt0 + v;
        sh_s[idx] = (gv < NV) ? shapedirs[gv * 30 + e] : 0.f;
        ex_s[idx] = (gv < NV) ? expr_dirs[gv * 30 + e] : 0.f;
    }
    for (int idx = tid; idx < 192; idx += 256) {
        int v = idx / 3, c = idx % 3;
        int gv = vt0 + v;
        vt_s[idx] = (gv < NV) ? v_template[gv * 3 + c] : 0.f;
    }
    for (int idx = tid; idx < 320; idx += 256) {
        int bb = idx / 10, k = idx % 10;
        be_s[idx]  = body_shape[(b0 + bb) * 10 + k];
        exb_s[idx] = expr_shape[(b0 + bb) * 10 + k];
    }
    for (int idx = tid; idx < 96; idx += 256)
        ts_s[idx] = tsl[b0 * 3 + idx];
    __syncthreads();

    // v_posed, k-outermost
    float vp[4][2][3];
    #pragma unroll
    for (int i = 0; i < 4; i++) {
        int bl = bg * 4 + i;
        #pragma unroll
        for (int s2 = 0; s2 < 2; s2++) {
            int vl = vloc + 32 * s2;
            #pragma unroll
            for (int c = 0; c < 3; c++)
                vp[i][s2][c] = c_s[bl * CS + vl * 3 + c] + vt_s[vl * 3 + c];
        }
    }
    #pragma unroll
    for (int k = 0; k < 10; k++) {
        float be4[4], exb4[4];
        #pragma unroll
        for (int i = 0; i < 4; i++) {
            be4[i]  = be_s[(bg * 4 + i) * 10 + k];
            exb4[i] = exb_s[(bg * 4 + i) * 10 + k];
        }
        #pragma unroll
        for (int s2 = 0; s2 < 2; s2++) {
            int vl = vloc + 32 * s2;
            #pragma unroll
            for (int c = 0; c < 3; c++) {
                float shv = sh_s[vl * 30 + c * 10 + k];
                float exv = ex_s[vl * 30 + c * 10 + k];
                #pragma unroll
                for (int i = 0; i < 4; i++)
                    vp[i][s2][c] += be4[i] * shv + exb4[i] * exv;
            }
        }
    }

    float o[4][2][3];
    #pragma unroll
    for (int i = 0; i < 4; i++)
        #pragma unroll
        for (int s2 = 0; s2 < 2; s2++)
            #pragma unroll
            for (int c = 0; c < 3; c++) o[i][s2][c] = 0.f;

    float* w_s   = smem;
    float* arg_s = smem + 3520;

    __syncthreads();
    for (int idx = tid; idx < 3520; idx += 256) {
        int v = idx / 55, j = idx % 55;
        int gv = vt0 + v;
        w_s[idx] = (gv < NV) ? lbsw[gv * 55 + j] : 0.f;
    }

    for (int j0 = 0; j0 < NJ; j0 += JG) {
        int njg = (NJ - j0 < JG) ? (NJ - j0) : JG;
        __syncthreads();
        for (int idx = tid; idx < BB * njg * 12; idx += 256) {
            int bb = idx / (njg * 12);
            int rem = idx % (njg * 12);
            arg_s[bb * (JG * 12) + rem] =
                g_Arel[(b0 + bb) * (NJ * 12) + (j0 * 12) + rem];
        }
        __syncthreads();
        for (int jj = 0; jj < njg; jj++) {
            int j = j0 + jj;
            #pragma unroll
            for (int i = 0; i < 4; i++) {
                int bl = bg * 4 + i;
                const float4* mq = (const float4*)(arg_s + bl * (JG * 12) + jj * 12);
                float4 m0 = mq[0];
                float4 m1 = mq[1];
                float4 m2 = mq[2];
                #pragma unroll
                for (int s2 = 0; s2 < 2; s2++) {
                    float w = w_s[(vloc + 32 * s2) * 55 + j];
                    float x = vp[i][s2][0], y = vp[i][s2][1], z = vp[i][s2][2];
                    o[i][s2][0] += w * (m0.x * x + m0.y * y + m0.z * z + m0.w);
                    o[i][s2][1] += w * (m1.x * x + m1.y * y + m1.z * z + m1.w);
                    o[i][s2][2] += w * (m2.x * x + m2.y * y + m2.z * z + m2.w);
                }
            }
        }
    }

    #pragma unroll
    for (int i = 0; i < 4; i++) {
        int bl = bg * 4 + i;
        int b = b0 + bl;
        #pragma unroll
        for (int s2 = 0; s2 < 2; s2++) {
            int v = vt0 + vloc + 32 * s2;
            if (v < NV) {
                #pragma unroll
                for (int c = 0; c < 3; c++)
                    out_verts[b * NC3 + v * 3 + c] = o[i][s2][c] + ts_s[bl * 3 + c];
            }
        }
    }
}

extern "C" void kernel_launch(void* const* d_in, const int* in_sizes, int n_in,
                              void* d_out, int out_size)
{
    const float* world_rot  = (const float*)d_in[0];
    const float* world_tsl  = (const float*)d_in[1];
    const float* body_shape = (const float*)d_in[2];
    const float* body_pose  = (const float*)d_in[3];
    const float* lhand      = (const float*)d_in[4];
    const float* rhand      = (const float*)d_in[5];
    const float* expr_shape = (const float*)d_in[6];
    const float* jaw        = (const float*)d_in[7];
    const float* leye       = (const float*)d_in[8];
    const float* reye       = (const float*)d_in[9];
    const float* v_template = (const float*)d_in[10];
    const float* shapedirs  = (const float*)d_in[11];
    const float* expr_dirs  = (const float*)d_in[12];
    const float* posedirs   = (const float*)d_in[13];
    const float* J_reg      = (const float*)d_in[14];
    const float* lbsw       = (const float*)d_in[15];
    float* out = (float*)d_out;

    jr_kernel<<<NJ, 256>>>(J_reg, v_template, shapedirs, expr_dirs);           // 1
    chain_kernel<<<BATCH, 64>>>(world_rot, body_pose, jaw, leye, reye, lhand,
                                rhand, body_shape, expr_shape, world_tsl, out); // 2 (+pf)
    gemmh_kernel<<<(NC3 + GC - 1) / GC, 256>>>(posedirs);                      // 3
    dim3 sgrid((NV + BV - 1) / BV, BATCH / BB);
    skin_kernel<<<sgrid, 256>>>(v_template, shapedirs, expr_dirs,
                                lbsw, body_shape, expr_shape, world_tsl, out); // 4 (profiled)
}

// round 13
// speedup vs baseline: 2.2650x; 2.2650x over previous
#include <cuda_runtime.h>
#include <cuda_fp16.h>
#include <cuda_bf16.h>

#define BATCH 256
#define NV 10475
#define NJ 55
#define PB 486            // pose basis = 54*9; 486 = 6*81
#define NC3 (NV*3)        // 31425
#define NC3P 31488
#define JOFF (BATCH*NC3)

// ---- scratch ----
#define CHUNK 96
#define NCH 110
__device__ float g_jr_partial[NCH * 3465];
__device__ float g_jreg[3465];              // (55,63): [vt|sh|ex]
__device__ unsigned g_pfh2[PB * 128];       // [k][bp]: half2 pair
__device__ float g_Arel[BATCH * NJ * 12];
__device__ float g_vpT[NC3P * BATCH];       // [col][b]

__constant__ int c_parents[NJ] = {
    -1, 0, 0, 0, 1, 2, 3, 4, 5, 6, 7, 8, 9, 9, 9, 12, 13, 14, 16, 17, 18, 19,
    15, 15, 15, 20, 25, 26, 20, 28, 29, 20, 31, 32, 20, 34, 35, 20, 37, 38,
    21, 40, 41, 21, 43, 44, 21, 46, 47, 21, 49, 50, 21, 52, 53};

__device__ __forceinline__ const float* joint_R(
    int j, int b, const float* wr, const float* bp, const float* jaw,
    const float* le, const float* re, const float* lh, const float* rh)
{
    if (j == 0)  return wr + b * 9;
    if (j <= 21) return bp + (b * 21 + (j - 1)) * 9;
    if (j == 22) return jaw + b * 9;
    if (j == 23) return le + b * 9;
    if (j == 24) return re + b * 9;
    if (j <= 39) return lh + (b * 15 + (j - 25)) * 9;
    return rh + (b * 15 + (j - 40)) * 9;
}

// ---- K1: partial JR @ [vt | sh | ex] (110-block smem-tiled; measured-fast) ----
__global__ __launch_bounds__(128) void jr_partial_kernel(
    const float* __restrict__ JR, const float* __restrict__ vt,
    const float* __restrict__ sh, const float* __restrict__ ex)
{
    __shared__ float jr_s[NJ * CHUNK];
    __shared__ float d_s[CHUNK * 63];
    int chunk = blockIdx.x;
    int v0 = chunk * CHUNK;
    int tid = threadIdx.x;

    for (int idx = tid; idx < NJ * CHUNK; idx += 128) {
        int j = idx / CHUNK, t = idx % CHUNK;
        int v = v0 + t;
        jr_s[idx] = (v < NV) ? JR[j * NV + v] : 0.f;
    }
    for (int idx = tid; idx < CHUNK * 63; idx += 128) {
        int t = idx / 63, c = idx % 63;
        int v = v0 + t;
        float val = 0.f;
        if (v < NV) {
            if (c < 3)       val = vt[v * 3 + c];
            else if (c < 33) val = sh[v * 30 + (c - 3)];
            else             val = ex[v * 30 + (c - 33)];
        }
        d_s[idx] = val;
    }
    __syncthreads();
    for (int o = tid; o < 3465; o += 128) {
        int j = o / 63, c = o % 63;
        float sum = 0.f;
        #pragma unroll 8
        for (int t = 0; t < CHUNK; t++)
            sum += jr_s[j * CHUNK + t] * d_s[t * 63 + c];
        g_jr_partial[chunk * 3465 + o] = sum;
    }
}

__global__ void jr_reduce_kernel()
{
    int o = blockIdx.x * 256 + threadIdx.x;
    if (o >= 3465) return;
    float s = 0.f;
    for (int ch = 0; ch < NCH; ch++) s += g_jr_partial[ch * 3465 + o];
    g_jreg[o] = s;
}

// ---- K3: chain + A_rel + joints out + pose-feature half write ----
__global__ __launch_bounds__(64) void chain_kernel(
    const float* __restrict__ wr, const float* __restrict__ bp,
    const float* __restrict__ jaw, const float* __restrict__ le,
    const float* __restrict__ re, const float* __restrict__ lh,
    const float* __restrict__ rh, const float* __restrict__ shape,
    const float* __restrict__ expr, const float* __restrict__ tsl,
    float* __restrict__ out)
{
    int b = blockIdx.x;
    int tid = threadIdx.x;
    __shared__ float R_s[NJ * 9];
    __shared__ float J_s[NJ * 3];
    __shared__ float rel_s[NJ * 3];
    __shared__ float A_s[NJ * 12];

    for (int idx = tid; idx < NJ * 9; idx += 64) {
        int j = idx / 9, e = idx % 9;
        R_s[idx] = joint_R(j, b, wr, bp, jaw, le, re, lh, rh)[e];
    }
    for (int idx = tid; idx < NJ * 3; idx += 64) {
        int j = idx / 3, c = idx % 3;
        const float* base = g_jreg + j * 63;
        float v = base[c];
        #pragma unroll
        for (int k = 0; k < 10; k++) v += base[3 + c * 10 + k] * shape[b * 10 + k];
        #pragma unroll
        for (int k = 0; k < 10; k++) v += base[33 + c * 10 + k] * expr[b * 10 + k];
        J_s[idx] = v;
    }
    __syncthreads();
    for (int idx = tid; idx < NJ * 3; idx += 64) {
        int j = idx / 3, c = idx % 3;
        rel_s[idx] = J_s[idx] - ((j > 0) ? J_s[c_parents[j] * 3 + c] : 0.f);
    }
    __syncthreads();

    if (tid < 12) {
        int r = tid / 4, c = tid % 4;
        A_s[r * 4 + c] = (c < 3) ? R_s[r * 3 + c] : rel_s[r];
        __syncwarp(0x0FFF);
        for (int i = 1; i < NJ; i++) {
            int p = c_parents[i];
            const float* Ap = A_s + p * 12;
            float v;
            if (c < 3)
                v = Ap[r * 4 + 0] * R_s[i * 9 + 0 + c] +
                    Ap[r * 4 + 1] * R_s[i * 9 + 3 + c] +
                    Ap[r * 4 + 2] * R_s[i * 9 + 6 + c];
            else
                v = Ap[r * 4 + 0] * rel_s[i * 3 + 0] +
                    Ap[r * 4 + 1] * rel_s[i * 3 + 1] +
                    Ap[r * 4 + 2] * rel_s[i * 3 + 2] + Ap[r * 4 + 3];
            A_s[i * 12 + r * 4 + c] = v;
            __syncwarp(0x0FFF);
        }
    }
    __syncthreads();

    for (int idx = tid; idx < NJ * 3; idx += 64) {
        int j = idx / 3, c = idx % 3;
        out[JOFF + b * (NJ * 3) + idx] = A_s[j * 12 + c * 4 + 3] + tsl[b * 3 + c];
    }
    for (int idx = tid; idx < NJ * 12; idx += 64) {
        int j = idx / 12, e = idx % 12, r = e / 4, c = e % 4;
        float v;
        if (c < 3)
            v = A_s[j * 12 + r * 4 + c];
        else
            v = A_s[j * 12 + r * 4 + 3] -
                (A_s[j * 12 + r * 4 + 0] * J_s[j * 3 + 0] +
                 A_s[j * 12 + r * 4 + 1] * J_s[j * 3 + 1] +
                 A_s[j * 12 + r * 4 + 2] * J_s[j * 3 + 2]);
        g_Arel[b * (NJ * 12) + idx] = v;
    }
    // pose feature (R - I) fp16, layout ((half*)g_pfh2)[k*256 + b]
    {
        __half* pfh = (__half*)g_pfh2;
        for (int idx = tid; idx < PB; idx += 64) {
            int e = idx % 9;
            float v = R_s[9 + idx] - ((e == 0 || e == 4 || e == 8) ? 1.f : 0.f);
            pfh[idx * 256 + b] = __float2half_rn(v);
        }
    }
}

// ---- K4 (profiled slot): HFMA2 GEMM (measured 171us, unchanged) ----
#define GC 24
#define GKC 81
#define GPROM 27

__global__ __launch_bounds__(256, 3) void gemmh_kernel(
    const float* __restrict__ posedirs)
{
    __shared__ __align__(16) unsigned pdh[GKC * GC];
    int tid = threadIdx.x;
    int w = tid >> 5, lane = tid & 31;
    int bpair = (w & 3) * 32 + lane;
    int cbase = (w >> 2) * 12;
    int col0 = blockIdx.x * GC;

    float2 accf[12];
    #pragma unroll
    for (int c = 0; c < 12; c++) accf[c] = make_float2(0.f, 0.f);

    for (int kc = 0; kc < 6; kc++) {
        int k0 = kc * GKC;
        for (int idx = tid; idx < GKC * GC; idx += 256) {
            int k = idx / GC, c = idx - k * GC;
            int gc = col0 + c;
            float v = (gc < NC3) ? posedirs[(k0 + k) * NC3 + gc] : 0.f;
            __half2 h = __half2half2(__float2half_rn(v));
            pdh[idx] = *(unsigned*)&h;
        }
        __syncthreads();

        const unsigned* pfb = g_pfh2 + k0 * 128 + bpair;
        for (int kp = 0; kp < GKC; kp += GPROM) {
            __half2 acch[12];
            #pragma unroll
            for (int c = 0; c < 12; c++) acch[c] = __half2half2(__ushort_as_half(0));
            #pragma unroll 9
            for (int k = 0; k < GPROM; k++) {
                int kk = kp + k;
                unsigned a2u = pfb[kk * 128];
                __half2 a2 = *(__half2*)&a2u;
                const uint4* prow = (const uint4*)(pdh + kk * GC + cbase);
                uint4 q0 = prow[0];
                uint4 q1 = prow[1];
                uint4 q2 = prow[2];
                unsigned pw[12] = {q0.x, q0.y, q0.z, q0.w,
                                   q1.x, q1.y, q1.z, q1.w,
                                   q2.x, q2.y, q2.z, q2.w};
                #pragma unroll
                for (int c = 0; c < 12; c++)
                    acch[c] = __hfma2(a2, *(__half2*)&pw[c], acch[c]);
            }
            #pragma unroll
            for (int c = 0; c < 12; c++) {
                float2 f = __half22float2(acch[c]);
                accf[c].x += f.x;
                accf[c].y += f.y;
            }
        }
        __syncthreads();
    }

    #pragma unroll
    for (int c = 0; c < 12; c++) {
        int gc = col0 + cbase + c;
        if (gc < NC3)
            *(float2*)(&g_vpT[gc * BATCH + 2 * bpair]) = accf[c];
    }
}

// ---- K5: shape blend + skinning (occ 3, measured 226us in R12) ----
#define BB 32
#define BV 64
#define JG 10
#define CS 193
#define SKIN_SMEM 10944

__global__ __launch_bounds__(256, 3) void skin_kernel(
    const float* __restrict__ v_template, const float* __restrict__ shapedirs,
    const float* __restrict__ expr_dirs, const float* __restrict__ lbsw,
    const float* __restrict__ body_shape, const float* __restrict__ expr_shape,
    const float* __restrict__ tsl, float* __restrict__ out_verts)
{
    int vt0 = blockIdx.x * BV;
    int b0 = blockIdx.y * BB;
    int tid = threadIdx.x;
    int vloc = tid & 31;
    int bg = tid >> 5;

    __shared__ __align__(16) float smem[SKIN_SMEM];
    float* c_s   = smem;
    float* sh_s  = smem + 6176;
    float* ex_s  = smem + 8096;
    float* vt_s  = smem + 10016;
    float* be_s  = smem + 10208;
    float* exb_s = smem + 10528;
    float* ts_s  = smem + 10848;

    int col0 = vt0 * 3;
    for (int idx = tid; idx < BB * 192; idx += 256) {
        int col = idx >> 5, bb = idx & 31;
        c_s[bb * CS + col] = g_vpT[(col0 + col) * BATCH + b0 + bb];
    }
    for (int idx = tid; idx < 1920; idx += 256) {
        int v = idx / 30, e = idx % 30;
        int gv = vt0 + v;
        sh_s[idx] = (gv < NV) ? shapedirs[gv * 30 + e] : 0.f;
        ex_s[idx] = (gv < NV) ? expr_dirs[gv * 30 + e] : 0.f;
    }
    for (int idx = tid; idx < 192; idx += 256) {
        int v = idx / 3, c = idx % 3;
        int gv = vt0 + v;
        vt_s[idx] = (gv < NV) ? v_template[gv * 3 + c] : 0.f;
    }
    for (int idx = tid; idx < 320; idx += 256) {
        int bb = idx / 10, k = idx % 10;
        be_s[idx]  = body_shape[(b0 + bb) * 10 + k];
        exb_s[idx] = expr_shape[(b0 + bb) * 10 + k];
    }
    for (int idx = tid; idx < 96; idx += 256)
        ts_s[idx] = tsl[b0 * 3 + idx];
    __syncthreads();

    float vp[4][2][3];
    #pragma unroll
    for (int i = 0; i < 4; i++) {
        int bl = bg * 4 + i;
        #pragma unroll
        for (int s2 = 0; s2 < 2; s2++) {
            int vl = vloc + 32 * s2;
            #pragma unroll
            for (int c = 0; c < 3; c++)
                vp[i][s2][c] = c_s[bl * CS + vl * 3 + c] + vt_s[vl * 3 + c];
        }
    }
    #pragma unroll
    for (int k = 0; k < 10; k++) {
        float be4[4], exb4[4];
        #pragma unroll
        for (int i = 0; i < 4; i++) {
            be4[i]  = be_s[(bg * 4 + i) * 10 + k];
            exb4[i] = exb_s[(bg * 4 + i) * 10 + k];
        }
        #pragma unroll
        for (int s2 = 0; s2 < 2; s2++) {
            int vl = vloc + 32 * s2;
            #pragma unroll
            for (int c = 0; c < 3; c++) {
                float shv = sh_s[vl * 30 + c * 10 + k];
                float exv = ex_s[vl * 30 + c * 10 + k];
                #pragma unroll
                for (int i = 0; i < 4; i++)
                    vp[i][s2][c] += be4[i] * shv + exb4[i] * exv;
            }
        }
    }

    float o[4][2][3];
    #pragma unroll
    for (int i = 0; i < 4; i++)
        #pragma unroll
        for (int s2 = 0; s2 < 2; s2++)
            #pragma unroll
            for (int c = 0; c < 3; c++) o[i][s2][c] = 0.f;

    float* w_s   = smem;
    float* arg_s = smem + 3520;

    __syncthreads();
    for (int idx = tid; idx < 3520; idx += 256) {
        int v = idx / 55, j = idx % 55;
        int gv = vt0 + v;
        w_s[idx] = (gv < NV) ? lbsw[gv * 55 + j] : 0.f;
    }

    for (int j0 = 0; j0 < NJ; j0 += JG) {
        int njg = (NJ - j0 < JG) ? (NJ - j0) : JG;
        __syncthreads();
        for (int idx = tid; idx < BB * njg * 12; idx += 256) {
            int bb = idx / (njg * 12);
            int rem = idx % (njg * 12);
            arg_s[bb * (JG * 12) + rem] =
                g_Arel[(b0 + bb) * (NJ * 12) + (j0 * 12) + rem];
        }
        __syncthreads();
        for (int jj = 0; jj < njg; jj++) {
            int j = j0 + jj;
            #pragma unroll
            for (int i = 0; i < 4; i++) {
                int bl = bg * 4 + i;
                const float4* mq = (const float4*)(arg_s + bl * (JG * 12) + jj * 12);
                float4 m0 = mq[0];
                float4 m1 = mq[1];
                float4 m2 = mq[2];
                #pragma unroll
                for (int s2 = 0; s2 < 2; s2++) {
                    float w = w_s[(vloc + 32 * s2) * 55 + j];
                    float x = vp[i][s2][0], y = vp[i][s2][1], z = vp[i][s2][2];
                    o[i][s2][0] += w * (m0.x * x + m0.y * y + m0.z * z + m0.w);
                    o[i][s2][1] += w * (m1.x * x + m1.y * y + m1.z * z + m1.w);
                    o[i][s2][2] += w * (m2.x * x + m2.y * y + m2.z * z + m2.w);
                }
            }
        }
    }

    #pragma unroll
    for (int i = 0; i < 4; i++) {
        int bl = bg * 4 + i;
        int b = b0 + bl;
        #pragma unroll
        for (int s2 = 0; s2 < 2; s2++) {
            int v = vt0 + vloc + 32 * s2;
            if (v < NV) {
                #pragma unroll
                for (int c = 0; c < 3; c++)
                    out_verts[b * NC3 + v * 3 + c] = o[i][s2][c] + ts_s[bl * 3 + c];
            }
        }
    }
}

extern "C" void kernel_launch(void* const* d_in, const int* in_sizes, int n_in,
                              void* d_out, int out_size)
{
    const float* world_rot  = (const float*)d_in[0];
    const float* world_tsl  = (const float*)d_in[1];
    const float* body_shape = (const float*)d_in[2];
    const float* body_pose  = (const float*)d_in[3];
    const float* lhand      = (const float*)d_in[4];
    const float* rhand      = (const float*)d_in[5];
    const float* expr_shape = (const float*)d_in[6];
    const float* jaw        = (const float*)d_in[7];
    const float* leye       = (const float*)d_in[8];
    const float* reye       = (const float*)d_in[9];
    const float* v_template = (const float*)d_in[10];
    const float* shapedirs  = (const float*)d_in[11];
    const float* expr_dirs  = (const float*)d_in[12];
    const float* posedirs   = (const float*)d_in[13];
    const float* J_reg      = (const float*)d_in[14];
    const float* lbsw       = (const float*)d_in[15];
    float* out = (float*)d_out;

    jr_partial_kernel<<<NCH, 128>>>(J_reg, v_template, shapedirs, expr_dirs);   // 1
    jr_reduce_kernel<<<(3465 + 255) / 256, 256>>>();                            // 2
    chain_kernel<<<BATCH, 64>>>(world_rot, body_pose, jaw, leye, reye, lhand,
                                rhand, body_shape, expr_shape, world_tsl, out); // 3 (+pf)
    gemmh_kernel<<<(NC3 + GC - 1) / GC, 256>>>(posedirs);                       // 4 (profiled)
    dim3 sgrid((NV + BV - 1) / BV, BATCH / BB);
    skin_kernel<<<sgrid, 256>>>(v_template, shapedirs, expr_dirs,
                                lbsw, body_shape, expr_shape, world_tsl, out);  // 5
}

// round 14
// speedup vs baseline: 2.6076x; 1.1513x over previous
#include <cuda_runtime.h>
#include <cuda_fp16.h>
#include <cuda_bf16.h>

#define BATCH 256
#define NV 10475
#define NJ 55
#define PB 486            // pose basis = 54*9; 486 = 6*81
#define NC3 (NV*3)        // 31425
#define NC3P 31488
#define JOFF (BATCH*NC3)

// ---- scratch ----
#define CHUNK 96
#define NCH 110
__device__ float g_jr_partial[NCH * 3465];
__device__ float g_jreg[3465];              // (55,63): [vt|sh|ex]
__device__ unsigned g_pfh2[PB * 128];       // [k][bp]: half2 pair
__device__ float g_Arel[BATCH * NJ * 12];
__device__ float g_vpT[NC3P * BATCH];       // [col][b]

__constant__ int c_parents[NJ] = {
    -1, 0, 0, 0, 1, 2, 3, 4, 5, 6, 7, 8, 9, 9, 9, 12, 13, 14, 16, 17, 18, 19,
    15, 15, 15, 20, 25, 26, 20, 28, 29, 20, 31, 32, 20, 34, 35, 20, 37, 38,
    21, 40, 41, 21, 43, 44, 21, 46, 47, 21, 49, 50, 21, 52, 53};

__device__ __forceinline__ const float* joint_R(
    int j, int b, const float* wr, const float* bp, const float* jaw,
    const float* le, const float* re, const float* lh, const float* rh)
{
    if (j == 0)  return wr + b * 9;
    if (j <= 21) return bp + (b * 21 + (j - 1)) * 9;
    if (j == 22) return jaw + b * 9;
    if (j == 23) return le + b * 9;
    if (j == 24) return re + b * 9;
    if (j <= 39) return lh + (b * 15 + (j - 25)) * 9;
    return rh + (b * 15 + (j - 40)) * 9;
}

// ---- K1: partial JR @ [vt | sh | ex] (measured-fast) ----
__global__ __launch_bounds__(128) void jr_partial_kernel(
    const float* __restrict__ JR, const float* __restrict__ vt,
    const float* __restrict__ sh, const float* __restrict__ ex)
{
    __shared__ float jr_s[NJ * CHUNK];
    __shared__ float d_s[CHUNK * 63];
    int chunk = blockIdx.x;
    int v0 = chunk * CHUNK;
    int tid = threadIdx.x;

    for (int idx = tid; idx < NJ * CHUNK; idx += 128) {
        int j = idx / CHUNK, t = idx % CHUNK;
        int v = v0 + t;
        jr_s[idx] = (v < NV) ? JR[j * NV + v] : 0.f;
    }
    for (int idx = tid; idx < CHUNK * 63; idx += 128) {
        int t = idx / 63, c = idx % 63;
        int v = v0 + t;
        float val = 0.f;
        if (v < NV) {
            if (c < 3)       val = vt[v * 3 + c];
            else if (c < 33) val = sh[v * 30 + (c - 3)];
            else             val = ex[v * 30 + (c - 33)];
        }
        d_s[idx] = val;
    }
    __syncthreads();
    for (int o = tid; o < 3465; o += 128) {
        int j = o / 63, c = o % 63;
        float sum = 0.f;
        #pragma unroll 8
        for (int t = 0; t < CHUNK; t++)
            sum += jr_s[j * CHUNK + t] * d_s[t * 63 + c];
        g_jr_partial[chunk * 3465 + o] = sum;
    }
}

__global__ void jr_reduce_kernel()
{
    int o = blockIdx.x * 256 + threadIdx.x;
    if (o >= 3465) return;
    float s = 0.f;
    for (int ch = 0; ch < NCH; ch++) s += g_jr_partial[ch * 3465 + o];
    g_jreg[o] = s;
}

// ---- K3: chain + A_rel + joints out + pose-feature half write ----
__global__ __launch_bounds__(64) void chain_kernel(
    const float* __restrict__ wr, const float* __restrict__ bp,
    const float* __restrict__ jaw, const float* __restrict__ le,
    const float* __restrict__ re, const float* __restrict__ lh,
    const float* __restrict__ rh, const float* __restrict__ shape,
    const float* __restrict__ expr, const float* __restrict__ tsl,
    float* __restrict__ out)
{
    int b = blockIdx.x;
    int tid = threadIdx.x;
    __shared__ float R_s[NJ * 9];
    __shared__ float J_s[NJ * 3];
    __shared__ float rel_s[NJ * 3];
    __shared__ float A_s[NJ * 12];

    for (int idx = tid; idx < NJ * 9; idx += 64) {
        int j = idx / 9, e = idx % 9;
        R_s[idx] = joint_R(j, b, wr, bp, jaw, le, re, lh, rh)[e];
    }
    for (int idx = tid; idx < NJ * 3; idx += 64) {
        int j = idx / 3, c = idx % 3;
        const float* base = g_jreg + j * 63;
        float v = base[c];
        #pragma unroll
        for (int k = 0; k < 10; k++) v += base[3 + c * 10 + k] * shape[b * 10 + k];
        #pragma unroll
        for (int k = 0; k < 10; k++) v += base[33 + c * 10 + k] * expr[b * 10 + k];
        J_s[idx] = v;
    }
    __syncthreads();
    for (int idx = tid; idx < NJ * 3; idx += 64) {
        int j = idx / 3, c = idx % 3;
        rel_s[idx] = J_s[idx] - ((j > 0) ? J_s[c_parents[j] * 3 + c] : 0.f);
    }
    __syncthreads();

    if (tid < 12) {
        int r = tid / 4, c = tid % 4;
        A_s[r * 4 + c] = (c < 3) ? R_s[r * 3 + c] : rel_s[r];
        __syncwarp(0x0FFF);
        for (int i = 1; i < NJ; i++) {
            int p = c_parents[i];
            const float* Ap = A_s + p * 12;
            float v;
            if (c < 3)
                v = Ap[r * 4 + 0] * R_s[i * 9 + 0 + c] +
                    Ap[r * 4 + 1] * R_s[i * 9 + 3 + c] +
                    Ap[r * 4 + 2] * R_s[i * 9 + 6 + c];
            else
                v = Ap[r * 4 + 0] * rel_s[i * 3 + 0] +
                    Ap[r * 4 + 1] * rel_s[i * 3 + 1] +
                    Ap[r * 4 + 2] * rel_s[i * 3 + 2] + Ap[r * 4 + 3];
            A_s[i * 12 + r * 4 + c] = v;
            __syncwarp(0x0FFF);
        }
    }
    __syncthreads();

    for (int idx = tid; idx < NJ * 3; idx += 64) {
        int j = idx / 3, c = idx % 3;
        out[JOFF + b * (NJ * 3) + idx] = A_s[j * 12 + c * 4 + 3] + tsl[b * 3 + c];
    }
    for (int idx = tid; idx < NJ * 12; idx += 64) {
        int j = idx / 12, e = idx % 12, r = e / 4, c = e % 4;
        float v;
        if (c < 3)
            v = A_s[j * 12 + r * 4 + c];
        else
            v = A_s[j * 12 + r * 4 + 3] -
                (A_s[j * 12 + r * 4 + 0] * J_s[j * 3 + 0] +
                 A_s[j * 12 + r * 4 + 1] * J_s[j * 3 + 1] +
                 A_s[j * 12 + r * 4 + 2] * J_s[j * 3 + 2]);
        g_Arel[b * (NJ * 12) + idx] = v;
    }
    {
        __half* pfh = (__half*)g_pfh2;
        for (int idx = tid; idx < PB; idx += 64) {
            int e = idx % 9;
            float v = R_s[9 + idx] - ((e == 0 || e == 4 || e == 8) ? 1.f : 0.f);
            pfh[idx * 256 + b] = __float2half_rn(v);
        }
    }
}

// ---- K4 (profiled slot): HFMA2 GEMM, GC=16 / occ 4 ----
#define GC 16
#define GKC 81
#define GPROM 27

__global__ __launch_bounds__(256, 4) void gemmh_kernel(
    const float* __restrict__ posedirs)
{
    __shared__ __align__(16) unsigned pdh[GKC * GC];   // [k][16] dup-half2
    int tid = threadIdx.x;
    int w = tid >> 5, lane = tid & 31;
    int bpair = (w & 3) * 32 + lane;     // 0..127
    int cbase = (w >> 2) * 8;            // 0 or 8
    int col0 = blockIdx.x * GC;

    float2 accf[8];
    #pragma unroll
    for (int c = 0; c < 8; c++) accf[c] = make_float2(0.f, 0.f);

    for (int kc = 0; kc < 6; kc++) {
        int k0 = kc * GKC;
        for (int idx = tid; idx < GKC * GC; idx += 256) {
            int k = idx >> 4, c = idx & 15;
            int gc = col0 + c;
            float v = (gc < NC3) ? posedirs[(k0 + k) * NC3 + gc] : 0.f;
            __half2 h = __half2half2(__float2half_rn(v));
            pdh[idx] = *(unsigned*)&h;
        }
        __syncthreads();

        const unsigned* pfb = g_pfh2 + k0 * 128 + bpair;
        for (int kp = 0; kp < GKC; kp += GPROM) {
            __half2 acch[8];
            #pragma unroll
            for (int c = 0; c < 8; c++) acch[c] = __half2half2(__ushort_as_half(0));
            #pragma unroll 9
            for (int k = 0; k < GPROM; k++) {
                int kk = kp + k;
                unsigned a2u = pfb[kk * 128];              // LDG.32 coalesced
                __half2 a2 = *(__half2*)&a2u;
                const uint4* prow = (const uint4*)(pdh + kk * GC + cbase);
                uint4 q0 = prow[0];                        // broadcast LDS.128
                uint4 q1 = prow[1];
                unsigned pw[8] = {q0.x, q0.y, q0.z, q0.w,
                                  q1.x, q1.y, q1.z, q1.w};
                #pragma unroll
                for (int c = 0; c < 8; c++)
                    acch[c] = __hfma2(a2, *(__half2*)&pw[c], acch[c]);
            }
            #pragma unroll
            for (int c = 0; c < 8; c++) {
                float2 f = __half22float2(acch[c]);
                accf[c].x += f.x;
                accf[c].y += f.y;
            }
        }
        __syncthreads();
    }

    #pragma unroll
    for (int c = 0; c < 8; c++) {
        int gc = col0 + cbase + c;
        if (gc < NC3)
            *(float2*)(&g_vpT[gc * BATCH + 2 * bpair]) = accf[c];
    }
}

// ---- K5: shape blend + skinning; JG=11 (55=5x11), fully unrolled j-group ----
#define BB 32
#define BV 64
#define JG 11
#define CS 193
#define SKIN_SMEM 10944

__global__ __launch_bounds__(256, 3) void skin_kernel(
    const float* __restrict__ v_template, const float* __restrict__ shapedirs,
    const float* __restrict__ expr_dirs, const float* __restrict__ lbsw,
    const float* __restrict__ body_shape, const float* __restrict__ expr_shape,
    const float* __restrict__ tsl, float* __restrict__ out_verts)
{
    int vt0 = blockIdx.x * BV;
    int b0 = blockIdx.y * BB;
    int tid = threadIdx.x;
    int vloc = tid & 31;
    int bg = tid >> 5;

    __shared__ __align__(16) float smem[SKIN_SMEM];
    float* c_s   = smem;
    float* sh_s  = smem + 6176;
    float* ex_s  = smem + 8096;
    float* vt_s  = smem + 10016;
    float* be_s  = smem + 10208;
    float* exb_s = smem + 10528;
    float* ts_s  = smem + 10848;

    int col0 = vt0 * 3;
    for (int idx = tid; idx < BB * 192; idx += 256) {
        int col = idx >> 5, bb = idx & 31;
        c_s[bb * CS + col] = g_vpT[(col0 + col) * BATCH + b0 + bb];
    }
    for (int idx = tid; idx < 1920; idx += 256) {
        int v = idx / 30, e = idx % 30;
        int gv = vt0 + v;
        sh_s[idx] = (gv < NV) ? shapedirs[gv * 30 + e] : 0.f;
        ex_s[idx] = (gv < NV) ? expr_dirs[gv * 30 + e] : 0.f;
    }
    for (int idx = tid; idx < 192; idx += 256) {
        int c = idx / 64, v = idx & 63;
        int gv = vt0 + v;
        vt_s[c * 64 + v] = (gv < NV) ? v_template[gv * 3 + c] : 0.f;
    }
    for (int idx = tid; idx < 320; idx += 256) {
        int bb = idx / 10, k = idx % 10;
        be_s[idx]  = body_shape[(b0 + bb) * 10 + k];
        exb_s[idx] = expr_shape[(b0 + bb) * 10 + k];
    }
    for (int idx = tid; idx < 96; idx += 256)
        ts_s[idx] = tsl[b0 * 3 + idx];
    __syncthreads();

    // v_posed, k-outermost
    float vp[4][2][3];
    #pragma unroll
    for (int i = 0; i < 4; i++) {
        int bl = bg * 4 + i;
        #pragma unroll
        for (int s2 = 0; s2 < 2; s2++) {
            int vl = vloc + 32 * s2;
            #pragma unroll
            for (int c = 0; c < 3; c++)
                vp[i][s2][c] = c_s[bl * CS + vl * 3 + c] + vt_s[c * 64 + vl];
        }
    }
    #pragma unroll
    for (int k = 0; k < 10; k++) {
        float be4[4], exb4[4];
        #pragma unroll
        for (int i = 0; i < 4; i++) {
            be4[i]  = be_s[(bg * 4 + i) * 10 + k];
            exb4[i] = exb_s[(bg * 4 + i) * 10 + k];
        }
        #pragma unroll
        for (int s2 = 0; s2 < 2; s2++) {
            int vl = vloc + 32 * s2;
            #pragma unroll
            for (int c = 0; c < 3; c++) {
                float shv = sh_s[vl * 30 + c * 10 + k];
                float exv = ex_s[vl * 30 + c * 10 + k];
                #pragma unroll
                for (int i = 0; i < 4; i++)
                    vp[i][s2][c] += be4[i] * shv + exb4[i] * exv;
            }
        }
    }

    float o[4][2][3];
    #pragma unroll
    for (int i = 0; i < 4; i++)
        #pragma unroll
        for (int s2 = 0; s2 < 2; s2++)
            #pragma unroll
            for (int c = 0; c < 3; c++) o[i][s2][c] = 0.f;

    float* w_s   = smem;            // [64][55] 3520
    float* arg_s = smem + 3520;     // [32][JG*12] = 32*132 = 4224

    __syncthreads();
    for (int idx = tid; idx < 3520; idx += 256) {
        int v = idx / 55, j = idx % 55;
        int gv = vt0 + v;
        w_s[idx] = (gv < NV) ? lbsw[gv * 55 + j] : 0.f;
    }

    for (int j0 = 0; j0 < NJ; j0 += JG) {        // 5 groups of exactly 11
        __syncthreads();
        for (int idx = tid; idx < BB * JG * 12; idx += 256) {
            int bb = idx / (JG * 12);
            int rem = idx - bb * (JG * 12);
            arg_s[bb * (JG * 12) + rem] =
                g_Arel[(b0 + bb) * (NJ * 12) + (j0 * 12) + rem];
        }
        __syncthreads();
        #pragma unroll
        for (int jj = 0; jj < JG; jj++) {        // compile-time jj -> imm offsets
            int j = j0 + jj;
            float wa = w_s[vloc * 55 + j];
            float wb = w_s[(vloc + 32) * 55 + j];
            #pragma unroll
            for (int i = 0; i < 4; i++) {
                const float4* mq =
                    (const float4*)(arg_s + (bg * 4 + i) * (JG * 12) + jj * 12);
                float4 m0 = mq[0];
                float4 m1 = mq[1];
                float4 m2 = mq[2];
                {
                    float x = vp[i][0][0], y = vp[i][0][1], z = vp[i][0][2];
                    o[i][0][0] += wa * (m0.x * x + m0.y * y + m0.z * z + m0.w);
                    o[i][0][1] += wa * (m1.x * x + m1.y * y + m1.z * z + m1.w);
                    o[i][0][2] += wa * (m2.x * x + m2.y * y + m2.z * z + m2.w);
                }
                {
                    float x = vp[i][1][0], y = vp[i][1][1], z = vp[i][1][2];
                    o[i][1][0] += wb * (m0.x * x + m0.y * y + m0.z * z + m0.w);
                    o[i][1][1] += wb * (m1.x * x + m1.y * y + m1.z * z + m1.w);
                    o[i][1][2] += wb * (m2.x * x + m2.y * y + m2.z * z + m2.w);
                }
            }
        }
    }

    #pragma unroll
    for (int i = 0; i < 4; i++) {
        int bl = bg * 4 + i;
        int b = b0 + bl;
        #pragma unroll
        for (int s2 = 0; s2 < 2; s2++) {
            int v = vt0 + vloc + 32 * s2;
            if (v < NV) {
                #pragma unroll
                for (int c = 0; c < 3; c++)
                    out_verts[b * NC3 + v * 3 + c] = o[i][s2][c] + ts_s[bl * 3 + c];
            }
        }
    }
}

extern "C" void kernel_launch(void* const* d_in, const int* in_sizes, int n_in,
                              void* d_out, int out_size)
{
    const float* world_rot  = (const float*)d_in[0];
    const float* world_tsl  = (const float*)d_in[1];
    const float* body_shape = (const float*)d_in[2];
    const float* body_pose  = (const float*)d_in[3];
    const float* lhand      = (const float*)d_in[4];
    const float* rhand      = (const float*)d_in[5];
    const float* expr_shape = (const float*)d_in[6];
    const float* jaw        = (const float*)d_in[7];
    const float* leye       = (const float*)d_in[8];
    const float* reye       = (const float*)d_in[9];
    const float* v_template = (const float*)d_in[10];
    const float* shapedirs  = (const float*)d_in[11];
    const float* expr_dirs  = (const float*)d_in[12];
    const float* posedirs   = (const float*)d_in[13];
    const float* J_reg      = (const float*)d_in[14];
    const float* lbsw       = (const float*)d_in[15];
    float* out = (float*)d_out;

    jr_partial_kernel<<<NCH, 128>>>(J_reg, v_template, shapedirs, expr_dirs);   // 1
    jr_reduce_kernel<<<(3465 + 255) / 256, 256>>>();                            // 2
    chain_kernel<<<BATCH, 64>>>(world_rot, body_pose, jaw, leye, reye, lhand,
                                rhand, body_shape, expr_shape, world_tsl, out); // 3
    gemmh_kernel<<<(NC3 + GC - 1) / GC, 256>>>(posedirs);                       // 4 (profiled)
    dim3 sgrid((NV + BV - 1) / BV, BATCH / BB);
    skin_kernel<<<sgrid, 256>>>(v_template, shapedirs, expr_dirs,
                                lbsw, body_shape, expr_shape, world_tsl, out);  // 5
}

// round 15
// speedup vs baseline: 2.6771x; 1.0266x over previous
#include <cuda_runtime.h>
#include <cuda_fp16.h>
#include <cuda_bf16.h>

#define BATCH 256
#define NV 10475
#define NJ 55
#define PB 486            // pose basis = 54*9; 486 = 6*81
#define NC3 (NV*3)        // 31425
#define NC3P 31488
#define JOFF (BATCH*NC3)

// ---- scratch ----
#define CHUNK 96
#define NCH 110
__device__ float g_jr_partial[NCH * 3465];
__device__ float g_jreg[3465];              // (55,63): [vt|sh|ex]
__device__ unsigned g_pfh2[PB * 128];       // [k][bp]: half2 pair
__device__ float g_Arel[BATCH * NJ * 12];
__device__ float g_vpT[NC3P * BATCH];       // [col][b]

__constant__ int c_parents[NJ] = {
    -1, 0, 0, 0, 1, 2, 3, 4, 5, 6, 7, 8, 9, 9, 9, 12, 13, 14, 16, 17, 18, 19,
    15, 15, 15, 20, 25, 26, 20, 28, 29, 20, 31, 32, 20, 34, 35, 20, 37, 38,
    21, 40, 41, 21, 43, 44, 21, 46, 47, 21, 49, 50, 21, 52, 53};

__device__ __forceinline__ const float* joint_R(
    int j, int b, const float* wr, const float* bp, const float* jaw,
    const float* le, const float* re, const float* lh, const float* rh)
{
    if (j == 0)  return wr + b * 9;
    if (j <= 21) return bp + (b * 21 + (j - 1)) * 9;
    if (j == 22) return jaw + b * 9;
    if (j == 23) return le + b * 9;
    if (j == 24) return re + b * 9;
    if (j <= 39) return lh + (b * 15 + (j - 25)) * 9;
    return rh + (b * 15 + (j - 40)) * 9;
}

// ---- K1: partial JR @ [vt | sh | ex] (measured-fast) ----
__global__ __launch_bounds__(128) void jr_partial_kernel(
    const float* __restrict__ JR, const float* __restrict__ vt,
    const float* __restrict__ sh, const float* __restrict__ ex)
{
    __shared__ float jr_s[NJ * CHUNK];
    __shared__ float d_s[CHUNK * 63];
    int chunk = blockIdx.x;
    int v0 = chunk * CHUNK;
    int tid = threadIdx.x;

    for (int idx = tid; idx < NJ * CHUNK; idx += 128) {
        int j = idx / CHUNK, t = idx % CHUNK;
        int v = v0 + t;
        jr_s[idx] = (v < NV) ? JR[j * NV + v] : 0.f;
    }
    for (int idx = tid; idx < CHUNK * 63; idx += 128) {
        int t = idx / 63, c = idx % 63;
        int v = v0 + t;
        float val = 0.f;
        if (v < NV) {
            if (c < 3)       val = vt[v * 3 + c];
            else if (c < 33) val = sh[v * 30 + (c - 3)];
            else             val = ex[v * 30 + (c - 33)];
        }
        d_s[idx] = val;
    }
    __syncthreads();
    for (int o = tid; o < 3465; o += 128) {
        int j = o / 63, c = o % 63;
        float sum = 0.f;
        #pragma unroll 8
        for (int t = 0; t < CHUNK; t++)
            sum += jr_s[j * CHUNK + t] * d_s[t * 63 + c];
        g_jr_partial[chunk * 3465 + o] = sum;
    }
}

__global__ void jr_reduce_kernel()
{
    int o = blockIdx.x * 256 + threadIdx.x;
    if (o >= 3465) return;
    float s = 0.f;
    for (int ch = 0; ch < NCH; ch++) s += g_jr_partial[ch * 3465 + o];
    g_jreg[o] = s;
}

// ---- K3: chain + A_rel + joints out + pose-feature half write ----
__global__ __launch_bounds__(64) void chain_kernel(
    const float* __restrict__ wr, const float* __restrict__ bp,
    const float* __restrict__ jaw, const float* __restrict__ le,
    const float* __restrict__ re, const float* __restrict__ lh,
    const float* __restrict__ rh, const float* __restrict__ shape,
    const float* __restrict__ expr, const float* __restrict__ tsl,
    float* __restrict__ out)
{
    int b = blockIdx.x;
    int tid = threadIdx.x;
    __shared__ float R_s[NJ * 9];
    __shared__ float J_s[NJ * 3];
    __shared__ float rel_s[NJ * 3];
    __shared__ float A_s[NJ * 12];

    for (int idx = tid; idx < NJ * 9; idx += 64) {
        int j = idx / 9, e = idx % 9;
        R_s[idx] = joint_R(j, b, wr, bp, jaw, le, re, lh, rh)[e];
    }
    for (int idx = tid; idx < NJ * 3; idx += 64) {
        int j = idx / 3, c = idx % 3;
        const float* base = g_jreg + j * 63;
        float v = base[c];
        #pragma unroll
        for (int k = 0; k < 10; k++) v += base[3 + c * 10 + k] * shape[b * 10 + k];
        #pragma unroll
        for (int k = 0; k < 10; k++) v += base[33 + c * 10 + k] * expr[b * 10 + k];
        J_s[idx] = v;
    }
    __syncthreads();
    for (int idx = tid; idx < NJ * 3; idx += 64) {
        int j = idx / 3, c = idx % 3;
        rel_s[idx] = J_s[idx] - ((j > 0) ? J_s[c_parents[j] * 3 + c] : 0.f);
    }
    __syncthreads();

    if (tid < 12) {
        int r = tid / 4, c = tid % 4;
        A_s[r * 4 + c] = (c < 3) ? R_s[r * 3 + c] : rel_s[r];
        __syncwarp(0x0FFF);
        for (int i = 1; i < NJ; i++) {
            int p = c_parents[i];
            const float* Ap = A_s + p * 12;
            float v;
            if (c < 3)
                v = Ap[r * 4 + 0] * R_s[i * 9 + 0 + c] +
                    Ap[r * 4 + 1] * R_s[i * 9 + 3 + c] +
                    Ap[r * 4 + 2] * R_s[i * 9 + 6 + c];
            else
                v = Ap[r * 4 + 0] * rel_s[i * 3 + 0] +
                    Ap[r * 4 + 1] * rel_s[i * 3 + 1] +
                    Ap[r * 4 + 2] * rel_s[i * 3 + 2] + Ap[r * 4 + 3];
            A_s[i * 12 + r * 4 + c] = v;
            __syncwarp(0x0FFF);
        }
    }
    __syncthreads();

    for (int idx = tid; idx < NJ * 3; idx += 64) {
        int j = idx / 3, c = idx % 3;
        out[JOFF + b * (NJ * 3) + idx] = A_s[j * 12 + c * 4 + 3] + tsl[b * 3 + c];
    }
    for (int idx = tid; idx < NJ * 12; idx += 64) {
        int j = idx / 12, e = idx % 12, r = e / 4, c = e % 4;
        float v;
        if (c < 3)
            v = A_s[j * 12 + r * 4 + c];
        else
            v = A_s[j * 12 + r * 4 + 3] -
                (A_s[j * 12 + r * 4 + 0] * J_s[j * 3 + 0] +
                 A_s[j * 12 + r * 4 + 1] * J_s[j * 3 + 1] +
                 A_s[j * 12 + r * 4 + 2] * J_s[j * 3 + 2]);
        g_Arel[b * (NJ * 12) + idx] = v;
    }
    {
        __half* pfh = (__half*)g_pfh2;
        for (int idx = tid; idx < PB; idx += 64) {
            int e = idx % 9;
            float v = R_s[9 + idx] - ((e == 0 || e == 4 || e == 8) ? 1.f : 0.f);
            pfh[idx * 256 + b] = __float2half_rn(v);
        }
    }
}

// ---- K4 (profiled slot): HFMA2 GEMM, GC=24 / occ 3 (R13-exact, 171us) ----
#define GC 24
#define GKC 81
#define GPROM 27

__global__ __launch_bounds__(256, 3) void gemmh_kernel(
    const float* __restrict__ posedirs)
{
    __shared__ __align__(16) unsigned pdh[GKC * GC];
    int tid = threadIdx.x;
    int w = tid >> 5, lane = tid & 31;
    int bpair = (w & 3) * 32 + lane;
    int cbase = (w >> 2) * 12;
    int col0 = blockIdx.x * GC;

    float2 accf[12];
    #pragma unroll
    for (int c = 0; c < 12; c++) accf[c] = make_float2(0.f, 0.f);

    for (int kc = 0; kc < 6; kc++) {
        int k0 = kc * GKC;
        for (int idx = tid; idx < GKC * GC; idx += 256) {
            int k = idx / GC, c = idx - k * GC;
            int gc = col0 + c;
            float v = (gc < NC3) ? posedirs[(k0 + k) * NC3 + gc] : 0.f;
            __half2 h = __half2half2(__float2half_rn(v));
            pdh[idx] = *(unsigned*)&h;
        }
        __syncthreads();

        const unsigned* pfb = g_pfh2 + k0 * 128 + bpair;
        for (int kp = 0; kp < GKC; kp += GPROM) {
            __half2 acch[12];
            #pragma unroll
            for (int c = 0; c < 12; c++) acch[c] = __half2half2(__ushort_as_half(0));
            #pragma unroll 9
            for (int k = 0; k < GPROM; k++) {
                int kk = kp + k;
                unsigned a2u = pfb[kk * 128];
                __half2 a2 = *(__half2*)&a2u;
                const uint4* prow = (const uint4*)(pdh + kk * GC + cbase);
                uint4 q0 = prow[0];
                uint4 q1 = prow[1];
                uint4 q2 = prow[2];
                unsigned pw[12] = {q0.x, q0.y, q0.z, q0.w,
                                   q1.x, q1.y, q1.z, q1.w,
                                   q2.x, q2.y, q2.z, q2.w};
                #pragma unroll
                for (int c = 0; c < 12; c++)
                    acch[c] = __hfma2(a2, *(__half2*)&pw[c], acch[c]);
            }
            #pragma unroll
            for (int c = 0; c < 12; c++) {
                float2 f = __half22float2(acch[c]);
                accf[c].x += f.x;
                accf[c].y += f.y;
            }
        }
        __syncthreads();
    }

    #pragma unroll
    for (int c = 0; c < 12; c++) {
        int gc = col0 + cbase + c;
        if (gc < NC3)
            *(float2*)(&g_vpT[gc * BATCH + 2 * bpair]) = accf[c];
    }
}

// ---- K5: shape blend + skinning; JG=11 fully unrolled (R14-exact, ~174us) ----
#define BB 32
#define BV 64
#define JG 11
#define CS 193
#define SKIN_SMEM 10944

__global__ __launch_bounds__(256, 3) void skin_kernel(
    const float* __restrict__ v_template, const float* __restrict__ shapedirs,
    const float* __restrict__ expr_dirs, const float* __restrict__ lbsw,
    const float* __restrict__ body_shape, const float* __restrict__ expr_shape,
    const float* __restrict__ tsl, float* __restrict__ out_verts)
{
    int vt0 = blockIdx.x * BV;
    int b0 = blockIdx.y * BB;
    int tid = threadIdx.x;
    int vloc = tid & 31;
    int bg = tid >> 5;

    __shared__ __align__(16) float smem[SKIN_SMEM];
    float* c_s   = smem;
    float* sh_s  = smem + 6176;
    float* ex_s  = smem + 8096;
    float* vt_s  = smem + 10016;
    float* be_s  = smem + 10208;
    float* exb_s = smem + 10528;
    float* ts_s  = smem + 10848;

    int col0 = vt0 * 3;
    for (int idx = tid; idx < BB * 192; idx += 256) {
        int col = idx >> 5, bb = idx & 31;
        c_s[bb * CS + col] = g_vpT[(col0 + col) * BATCH + b0 + bb];
    }
    for (int idx = tid; idx < 1920; idx += 256) {
        int v = idx / 30, e = idx % 30;
        int gv = vt0 + v;
        sh_s[idx] = (gv < NV) ? shapedirs[gv * 30 + e] : 0.f;
        ex_s[idx] = (gv < NV) ? expr_dirs[gv * 30 + e] : 0.f;
    }
    for (int idx = tid; idx < 192; idx += 256) {
        int c = idx / 64, v = idx & 63;
        int gv = vt0 + v;
        vt_s[c * 64 + v] = (gv < NV) ? v_template[gv * 3 + c] : 0.f;
    }
    for (int idx = tid; idx < 320; idx += 256) {
        int bb = idx / 10, k = idx % 10;
        be_s[idx]  = body_shape[(b0 + bb) * 10 + k];
        exb_s[idx] = expr_shape[(b0 + bb) * 10 + k];
    }
    for (int idx = tid; idx < 96; idx += 256)
        ts_s[idx] = tsl[b0 * 3 + idx];
    __syncthreads();

    float vp[4][2][3];
    #pragma unroll
    for (int i = 0; i < 4; i++) {
        int bl = bg * 4 + i;
        #pragma unroll
        for (int s2 = 0; s2 < 2; s2++) {
            int vl = vloc + 32 * s2;
            #pragma unroll
            for (int c = 0; c < 3; c++)
                vp[i][s2][c] = c_s[bl * CS + vl * 3 + c] + vt_s[c * 64 + vl];
        }
    }
    #pragma unroll
    for (int k = 0; k < 10; k++) {
        float be4[4], exb4[4];
        #pragma unroll
        for (int i = 0; i < 4; i++) {
            be4[i]  = be_s[(bg * 4 + i) * 10 + k];
            exb4[i] = exb_s[(bg * 4 + i) * 10 + k];
        }
        #pragma unroll
        for (int s2 = 0; s2 < 2; s2++) {
            int vl = vloc + 32 * s2;
            #pragma unroll
            for (int c = 0; c < 3; c++) {
                float shv = sh_s[vl * 30 + c * 10 + k];
                float exv = ex_s[vl * 30 + c * 10 + k];
                #pragma unroll
                for (int i = 0; i < 4; i++)
                    vp[i][s2][c] += be4[i] * shv + exb4[i] * exv;
            }
        }
    }

    float o[4][2][3];
    #pragma unroll
    for (int i = 0; i < 4; i++)
        #pragma unroll
        for (int s2 = 0; s2 < 2; s2++)
            #pragma unroll
            for (int c = 0; c < 3; c++) o[i][s2][c] = 0.f;

    float* w_s   = smem;            // [64][55]
    float* arg_s = smem + 3520;     // [32][JG*12]

    __syncthreads();
    for (int idx = tid; idx < 3520; idx += 256) {
        int v = idx / 55, j = idx % 55;
        int gv = vt0 + v;
        w_s[idx] = (gv < NV) ? lbsw[gv * 55 + j] : 0.f;
    }

    for (int j0 = 0; j0 < NJ; j0 += JG) {
        __syncthreads();
        for (int idx = tid; idx < BB * JG * 12; idx += 256) {
            int bb = idx / (JG * 12);
            int rem = idx - bb * (JG * 12);
            arg_s[bb * (JG * 12) + rem] =
                g_Arel[(b0 + bb) * (NJ * 12) + (j0 * 12) + rem];
        }
        __syncthreads();
        #pragma unroll
        for (int jj = 0; jj < JG; jj++) {
            int j = j0 + jj;
            float wa = w_s[vloc * 55 + j];
            float wb = w_s[(vloc + 32) * 55 + j];
            #pragma unroll
            for (int i = 0; i < 4; i++) {
                const float4* mq =
                    (const float4*)(arg_s + (bg * 4 + i) * (JG * 12) + jj * 12);
                float4 m0 = mq[0];
                float4 m1 = mq[1];
                float4 m2 = mq[2];
                {
                    float x = vp[i][0][0], y = vp[i][0][1], z = vp[i][0][2];
                    o[i][0][0] += wa * (m0.x * x + m0.y * y + m0.z * z + m0.w);
                    o[i][0][1] += wa * (m1.x * x + m1.y * y + m1.z * z + m1.w);
                    o[i][0][2] += wa * (m2.x * x + m2.y * y + m2.z * z + m2.w);
                }
                {
                    float x = vp[i][1][0], y = vp[i][1][1], z = vp[i][1][2];
                    o[i][1][0] += wb * (m0.x * x + m0.y * y + m0.z * z + m0.w);
                    o[i][1][1] += wb * (m1.x * x + m1.y * y + m1.z * z + m1.w);
                    o[i][1][2] += wb * (m2.x * x + m2.y * y + m2.z * z + m2.w);
                }
            }
        }
    }

    #pragma unroll
    for (int i = 0; i < 4; i++) {
        int bl = bg * 4 + i;
        int b = b0 + bl;
        #pragma unroll
        for (int s2 = 0; s2 < 2; s2++) {
            int v = vt0 + vloc + 32 * s2;
            if (v < NV) {
                #pragma unroll
                for (int c = 0; c < 3; c++)
                    out_verts[b * NC3 + v * 3 + c] = o[i][s2][c] + ts_s[bl * 3 + c];
            }
        }
    }
}

extern "C" void kernel_launch(void* const* d_in, const int* in_sizes, int n_in,
                              void* d_out, int out_size)
{
    const float* world_rot  = (const float*)d_in[0];
    const float* world_tsl  = (const float*)d_in[1];
    const float* body_shape = (const float*)d_in[2];
    const float* body_pose  = (const float*)d_in[3];
    const float* lhand      = (const float*)d_in[4];
    const float* rhand      = (const float*)d_in[5];
    const float* expr_shape = (const float*)d_in[6];
    const float* jaw        = (const float*)d_in[7];
    const float* leye       = (const float*)d_in[8];
    const float* reye       = (const float*)d_in[9];
    const float* v_template = (const float*)d_in[10];
    const float* shapedirs  = (const float*)d_in[11];
    const float* expr_dirs  = (const float*)d_in[12];
    const float* posedirs   = (const float*)d_in[13];
    const float* J_reg      = (const float*)d_in[14];
    const float* lbsw       = (const float*)d_in[15];
    float* out = (float*)d_out;

    jr_partial_kernel<<<NCH, 128>>>(J_reg, v_template, shapedirs, expr_dirs);   // 1
    jr_reduce_kernel<<<(3465 + 255) / 256, 256>>>();                            // 2
    chain_kernel<<<BATCH, 64>>>(world_rot, body_pose, jaw, leye, reye, lhand,
                                rhand, body_shape, expr_shape, world_tsl, out); // 3
    gemmh_kernel<<<(NC3 + GC - 1) / GC, 256>>>(posedirs);                       // 4 (profiled)
    dim3 sgrid((NV + BV - 1) / BV, BATCH / BB);
    skin_kernel<<<sgrid, 256>>>(v_template, shapedirs, expr_dirs,
                                lbsw, body_shape, expr_shape, world_tsl, out);  // 5
}